// round 1
// baseline (speedup 1.0000x reference)
#include <cuda_runtime.h>
#include <cuda_bf16.h>
#include <math.h>
#include <stdint.h>

// ----------------------------------------------------------------------------
// Model constants
// ----------------------------------------------------------------------------
#define Bc   4
#define Tc   1024
#define Nc   (Bc * Tc)        // 4096 tokens
#define Ec   768
#define FFc  3072
#define Vc   32000
#define Hc   6
#define HDc  128
#define Lc   6
#define NVc  ((size_t)Nc * Vc)

// ----------------------------------------------------------------------------
// Scratch (device globals; no allocation allowed)
// ----------------------------------------------------------------------------
__device__ float g_x [Nc * Ec];
__device__ float g_h [Nc * Ec];
__device__ float g_q [Nc * Ec];
__device__ float g_k [Nc * Ec];
__device__ float g_v [Nc * Ec];
__device__ float g_o [Nc * Ec];
__device__ float g_ff[Nc * FFc];
__device__ float g_logits_fallback[Nc * (size_t)Vc];
__device__ int   g_idx[Nc];
__device__ int   g_tgt[Nc];
__device__ float g_rowloss[Nc];
__device__ int   g_is64;

// ----------------------------------------------------------------------------
// idx dtype detection + conversion (jax int64 may or may not be downcast)
// ----------------------------------------------------------------------------
__global__ void detect_idx_kernel(const void* idx_raw) {
    const long long* p = (const long long*)idx_raw;
    int t = threadIdx.x;
    bool ok = true;
    for (int i = t; i < 64; i += 32) {
        long long v = p[i];
        if (v < 0 || v >= Vc) ok = false;
    }
    unsigned m = __ballot_sync(0xffffffffu, ok);
    if (t == 0) g_is64 = (m == 0xffffffffu) ? 1 : 0;
}

__global__ void convert_idx_kernel(const void* idxp, const void* tgtp) {
    int i = blockIdx.x * blockDim.x + threadIdx.x;
    if (i >= Nc) return;
    if (g_is64) {
        g_idx[i] = (int)((const long long*)idxp)[i];
        g_tgt[i] = (int)((const long long*)tgtp)[i];
    } else {
        g_idx[i] = ((const int*)idxp)[i];
        g_tgt[i] = ((const int*)tgtp)[i];
    }
}

// ----------------------------------------------------------------------------
// Embedding: x[n,e] = tok_emb[idx[n], e] + pos_emb[n % T, e]
// ----------------------------------------------------------------------------
__global__ void embed_kernel(const float* __restrict__ tok,
                             const float* __restrict__ pos,
                             float* __restrict__ x) {
    int gid = blockIdx.x * blockDim.x + threadIdx.x;
    if (gid >= Nc * Ec) return;
    int row = gid / Ec;
    int e   = gid - row * Ec;
    int t   = row & (Tc - 1);
    x[gid] = tok[(size_t)g_idx[row] * Ec + e] + pos[(size_t)t * Ec + e];
}

// ----------------------------------------------------------------------------
// LayerNorm (row-per-block, E=768, 256 threads -> 3 elems/thread)
// ----------------------------------------------------------------------------
__global__ __launch_bounds__(256) void ln_kernel(const float* __restrict__ x,
                                                 const float* __restrict__ gw,
                                                 const float* __restrict__ gb,
                                                 float* __restrict__ out) {
    int row = blockIdx.x, t = threadIdx.x;
    const float* xr = x + (size_t)row * Ec;
    float v0 = xr[t], v1 = xr[t + 256], v2 = xr[t + 512];
    float s  = v0 + v1 + v2;
    float sq = fmaf(v0, v0, fmaf(v1, v1, v2 * v2));

    int lane = t & 31, wp = t >> 5;
    #pragma unroll
    for (int o = 16; o; o >>= 1) {
        s  += __shfl_xor_sync(0xffffffffu, s, o);
        sq += __shfl_xor_sync(0xffffffffu, sq, o);
    }
    __shared__ float shs[8], shq[8];
    if (lane == 0) { shs[wp] = s; shq[wp] = sq; }
    __syncthreads();
    s = 0.f; sq = 0.f;
    #pragma unroll
    for (int i = 0; i < 8; ++i) { s += shs[i]; sq += shq[i]; }

    const float invE = 1.0f / Ec;
    float mu   = s * invE;
    float var  = sq * invE - mu * mu;
    float rstd = rsqrtf(var + 1e-5f);

    float* orow = out + (size_t)row * Ec;
    orow[t]       = (v0 - mu) * rstd * gw[t]       + gb[t];
    orow[t + 256] = (v1 - mu) * rstd * gw[t + 256] + gb[t + 256];
    orow[t + 512] = (v2 - mu) * rstd * gw[t + 512] + gb[t + 512];
}

// ----------------------------------------------------------------------------
// SGEMM: C[M,N] = A[M,K] @ B[K,N] (+bias, optional relu / residual-add)
// 128x128 tile, BK=8, 256 threads, 8x8 per thread.
// Requires M%128==0, N%128==0, K%8==0 (true for all calls here).
// ----------------------------------------------------------------------------
#define EPI_BIAS 0
#define EPI_RELU 1
#define EPI_RES  2

template <int EPI>
__global__ __launch_bounds__(256) void sgemm128(const float* __restrict__ A,
                                                const float* __restrict__ B,
                                                const float* __restrict__ bias,
                                                float* __restrict__ C,
                                                int M, int N, int K) {
    __shared__ __align__(16) float As[8][128];
    __shared__ __align__(16) float Bs[8][128];

    int tid = threadIdx.x;
    int col0 = blockIdx.x * 128;
    int row0 = blockIdx.y * 128;

    int aRow = tid >> 1;
    int aCol = (tid & 1) * 4;
    int bRow = tid >> 5;
    int bCol = (tid & 31) * 4;

    int tx = tid & 15;        // 0..15 -> 128 cols
    int ty = tid >> 4;        // 0..15 -> 128 rows

    float acc[8][8];
    #pragma unroll
    for (int i = 0; i < 8; ++i)
        #pragma unroll
        for (int j = 0; j < 8; ++j) acc[i][j] = 0.f;

    for (int k0 = 0; k0 < K; k0 += 8) {
        float4 av = *(const float4*)(A + (size_t)(row0 + aRow) * K + k0 + aCol);
        As[aCol + 0][aRow] = av.x;
        As[aCol + 1][aRow] = av.y;
        As[aCol + 2][aRow] = av.z;
        As[aCol + 3][aRow] = av.w;
        *(float4*)&Bs[bRow][bCol] =
            *(const float4*)(B + (size_t)(k0 + bRow) * N + col0 + bCol);
        __syncthreads();

        #pragma unroll
        for (int kk = 0; kk < 8; ++kk) {
            float4 a0 = *(const float4*)&As[kk][ty * 4];
            float4 a1 = *(const float4*)&As[kk][64 + ty * 4];
            float4 b0 = *(const float4*)&Bs[kk][tx * 4];
            float4 b1 = *(const float4*)&Bs[kk][64 + tx * 4];
            float ar[8] = {a0.x, a0.y, a0.z, a0.w, a1.x, a1.y, a1.z, a1.w};
            float br[8] = {b0.x, b0.y, b0.z, b0.w, b1.x, b1.y, b1.z, b1.w};
            #pragma unroll
            for (int i = 0; i < 8; ++i)
                #pragma unroll
                for (int j = 0; j < 8; ++j)
                    acc[i][j] = fmaf(ar[i], br[j], acc[i][j]);
        }
        __syncthreads();
    }

    #pragma unroll
    for (int i = 0; i < 8; ++i) {
        int r = row0 + ((i < 4) ? (ty * 4 + i) : (64 + ty * 4 + i - 4));
        float* crow = C + (size_t)r * N;
        #pragma unroll
        for (int j = 0; j < 8; ++j) {
            int c = col0 + ((j < 4) ? (tx * 4 + j) : (64 + tx * 4 + j - 4));
            float v = acc[i][j] + bias[c];
            if (EPI == EPI_RELU) v = fmaxf(v, 0.f);
            if (EPI == EPI_RES)  v += crow[c];
            crow[c] = v;
        }
    }
}

// ----------------------------------------------------------------------------
// Causal attention: one block per (b, h, qpos). 128 threads.
// Scores in shared (<=1024), K/V staged in 32x128 shared tiles (pad 129).
// ----------------------------------------------------------------------------
__global__ __launch_bounds__(128) void attn_kernel(const float* __restrict__ Q,
                                                   const float* __restrict__ K,
                                                   const float* __restrict__ V,
                                                   float* __restrict__ O) {
    int qpos = blockIdx.x, h = blockIdx.y, b = blockIdx.z;
    int t = threadIdx.x, lane = t & 31, wp = t >> 5;

    __shared__ float sQ[128];
    __shared__ float sS[Tc];
    __shared__ float sT[32][129];
    __shared__ float sPart[32][4];
    __shared__ float sW[4];

    const size_t base = (size_t)b * Tc * Ec + (size_t)h * HDc;
    sQ[t] = Q[base + (size_t)qpos * Ec + t];
    __syncthreads();

    int nk = qpos + 1;
    const float scale = 0.08838834764831845f; // 1/sqrt(128)

    // ---- scores ----
    for (int c0 = 0; c0 < nk; c0 += 32) {
        int rows = min(32, nk - c0);
        for (int r = wp; r < rows; r += 4) {
            const float* kr = K + base + (size_t)(c0 + r) * Ec;
            #pragma unroll
            for (int j = 0; j < 4; ++j) sT[r][lane + 32 * j] = kr[lane + 32 * j];
        }
        __syncthreads();
        if (lane < rows) {
            float sum = 0.f;
            #pragma unroll
            for (int dd = 0; dd < 32; ++dd)
                sum = fmaf(sQ[wp * 32 + dd], sT[lane][wp * 32 + dd], sum);
            sPart[lane][wp] = sum;
        }
        __syncthreads();
        if (t < rows)
            sS[c0 + t] = (sPart[t][0] + sPart[t][1] + sPart[t][2] + sPart[t][3]) * scale;
        __syncthreads();
    }

    // ---- softmax over sS[0..nk) ----
    float m = -1e30f;
    for (int i = t; i < nk; i += 128) m = fmaxf(m, sS[i]);
    #pragma unroll
    for (int o = 16; o; o >>= 1) m = fmaxf(m, __shfl_xor_sync(0xffffffffu, m, o));
    if (lane == 0) sW[wp] = m;
    __syncthreads();
    m = fmaxf(fmaxf(sW[0], sW[1]), fmaxf(sW[2], sW[3]));
    __syncthreads();

    float sum = 0.f;
    for (int i = t; i < nk; i += 128) {
        float p = expf(sS[i] - m);
        sS[i] = p;
        sum += p;
    }
    #pragma unroll
    for (int o = 16; o; o >>= 1) sum += __shfl_xor_sync(0xffffffffu, sum, o);
    if (lane == 0) sW[wp] = sum;
    __syncthreads();
    sum = sW[0] + sW[1] + sW[2] + sW[3];
    float inv = 1.0f / sum;

    // ---- P @ V ----
    float acc = 0.f;
    for (int c0 = 0; c0 < nk; c0 += 32) {
        int rows = min(32, nk - c0);
        __syncthreads();
        for (int r = wp; r < rows; r += 4) {
            const float* vr = V + base + (size_t)(c0 + r) * Ec;
            #pragma unroll
            for (int j = 0; j < 4; ++j) sT[r][lane + 32 * j] = vr[lane + 32 * j];
        }
        __syncthreads();
        for (int r = 0; r < rows; ++r)
            acc = fmaf(sS[c0 + r], sT[r][t], acc);
    }
    O[base + (size_t)qpos * Ec + t] = acc * inv;
}

// ----------------------------------------------------------------------------
// Loss: per-row log-softmax + target gather; deterministic reduce
// ----------------------------------------------------------------------------
__global__ __launch_bounds__(256) void loss_rows_kernel(const float* __restrict__ logits,
                                                        float* __restrict__ rowloss) {
    int row = blockIdx.x, t = threadIdx.x;
    int lane = t & 31, wp = t >> 5;
    const float* lr = logits + (size_t)row * Vc;
    __shared__ float sh[8];

    float m = -1e30f;
    for (int i = t; i < Vc; i += 256) m = fmaxf(m, lr[i]);
    #pragma unroll
    for (int o = 16; o; o >>= 1) m = fmaxf(m, __shfl_xor_sync(0xffffffffu, m, o));
    if (lane == 0) sh[wp] = m;
    __syncthreads();
    m = sh[0];
    #pragma unroll
    for (int i = 1; i < 8; ++i) m = fmaxf(m, sh[i]);
    __syncthreads();

    float s = 0.f;
    for (int i = t; i < Vc; i += 256) s += expf(lr[i] - m);
    #pragma unroll
    for (int o = 16; o; o >>= 1) s += __shfl_xor_sync(0xffffffffu, s, o);
    if (lane == 0) sh[wp] = s;
    __syncthreads();
    if (t == 0) {
        s = 0.f;
        #pragma unroll
        for (int i = 0; i < 8; ++i) s += sh[i];
        int tg = g_tgt[row];
        rowloss[row] = -(lr[tg] - m - logf(s));
    }
}

__global__ __launch_bounds__(256) void loss_final_kernel(const float* __restrict__ rowloss,
                                                         float* __restrict__ out) {
    int t = threadIdx.x, lane = t & 31, wp = t >> 5;
    float s = 0.f;
    for (int i = t; i < Nc; i += 256) s += rowloss[i];
    #pragma unroll
    for (int o = 16; o; o >>= 1) s += __shfl_xor_sync(0xffffffffu, s, o);
    __shared__ float sh[8];
    if (lane == 0) sh[wp] = s;
    __syncthreads();
    if (t == 0) {
        s = 0.f;
        #pragma unroll
        for (int i = 0; i < 8; ++i) s += sh[i];
        out[0] = s * (1.0f / Nc);
    }
}

// ----------------------------------------------------------------------------
// Host launch
// ----------------------------------------------------------------------------
static float* sym_addr(const void* s) {
    void* p = nullptr;
    cudaGetSymbolAddress(&p, s);
    return (float*)p;
}

extern "C" void kernel_launch(void* const* d_in, const int* in_sizes, int n_in,
                              void* d_out, int out_size) {
    const void*  idxp = d_in[0];
    const void*  tgtp = d_in[1];
    const float* tok  = (const float*)d_in[2];
    const float* pos  = (const float*)d_in[3];
    const float* Wq   = (const float*)d_in[4];
    const float* bq   = (const float*)d_in[5];
    const float* Wk   = (const float*)d_in[6];
    const float* bk   = (const float*)d_in[7];
    const float* Wv   = (const float*)d_in[8];
    const float* bv   = (const float*)d_in[9];
    const float* Wo   = (const float*)d_in[10];
    const float* bo   = (const float*)d_in[11];
    const float* w1   = (const float*)d_in[12];
    const float* b1   = (const float*)d_in[13];
    const float* w2   = (const float*)d_in[14];
    const float* b2   = (const float*)d_in[15];
    const float* ln1s = (const float*)d_in[16];
    const float* ln1b = (const float*)d_in[17];
    const float* ln2s = (const float*)d_in[18];
    const float* ln2b = (const float*)d_in[19];
    const float* lnfs = (const float*)d_in[20];
    const float* lnfb = (const float*)d_in[21];
    const float* Wlm  = (const float*)d_in[22];
    const float* blm  = (const float*)d_in[23];

    float* x  = sym_addr(g_x);
    float* h  = sym_addr(g_h);
    float* q  = sym_addr(g_q);
    float* k  = sym_addr(g_k);
    float* v  = sym_addr(g_v);
    float* o  = sym_addr(g_o);
    float* ff = sym_addr(g_ff);
    float* rowloss = sym_addr(g_rowloss);

    // logits destination: d_out when it can hold them, else fallback scratch
    float* logits = ((size_t)out_size >= NVc) ? (float*)d_out
                                              : sym_addr(g_logits_fallback);

    detect_idx_kernel<<<1, 32>>>(idxp);
    convert_idx_kernel<<<(Nc + 255) / 256, 256>>>(idxp, tgtp);
    embed_kernel<<<(Nc * Ec + 255) / 256, 256>>>(tok, pos, x);

    dim3 gE(Ec / 128, Nc / 128);    // [4096 x 768]
    dim3 gF(FFc / 128, Nc / 128);   // [4096 x 3072]
    dim3 gV(Vc / 128, Nc / 128);    // [4096 x 32000]
    dim3 gAttn(Tc, Hc, Bc);

    for (int l = 0; l < Lc; ++l) {
        const float* Wql = Wq + (size_t)l * Ec * Ec;
        const float* Wkl = Wk + (size_t)l * Ec * Ec;
        const float* Wvl = Wv + (size_t)l * Ec * Ec;
        const float* Wol = Wo + (size_t)l * Ec * Ec;
        const float* w1l = w1 + (size_t)l * Ec * FFc;
        const float* w2l = w2 + (size_t)l * FFc * Ec;

        ln_kernel<<<Nc, 256>>>(x, ln1s + l * Ec, ln1b + l * Ec, h);
        sgemm128<EPI_BIAS><<<gE, 256>>>(h, Wql, bq + l * Ec, q, Nc, Ec, Ec);
        sgemm128<EPI_BIAS><<<gE, 256>>>(h, Wkl, bk + l * Ec, k, Nc, Ec, Ec);
        sgemm128<EPI_BIAS><<<gE, 256>>>(h, Wvl, bv + l * Ec, v, Nc, Ec, Ec);
        attn_kernel<<<gAttn, 128>>>(q, k, v, o);
        sgemm128<EPI_RES><<<gE, 256>>>(o, Wol, bo + l * Ec, x, Nc, Ec, Ec);
        ln_kernel<<<Nc, 256>>>(x, ln2s + l * Ec, ln2b + l * Ec, h);
        sgemm128<EPI_RELU><<<gF, 256>>>(h, w1l, b1 + l * FFc, ff, Nc, FFc, Ec);
        sgemm128<EPI_RES><<<gE, 256>>>(ff, w2l, b2 + l * Ec, x, Nc, Ec, FFc);
    }

    ln_kernel<<<Nc, 256>>>(x, lnfs, lnfb, h);
    sgemm128<EPI_BIAS><<<gV, 256>>>(h, Wlm, blm, logits, Nc, Vc, Ec);

    loss_rows_kernel<<<Nc, 256>>>(logits, rowloss);
    if ((size_t)out_size >= NVc + 1) {
        loss_final_kernel<<<1, 256>>>(rowloss, (float*)d_out + NVc);
    } else if ((size_t)out_size < NVc) {
        // output is just the loss scalar
        loss_final_kernel<<<1, 256>>>(rowloss, (float*)d_out);
    }
}

// round 3
// speedup vs baseline: 1.4354x; 1.4354x over previous
#include <cuda_runtime.h>
#include <cuda_bf16.h>
#include <math.h>
#include <stdint.h>

// ----------------------------------------------------------------------------
// Model constants
// ----------------------------------------------------------------------------
#define Bc   4
#define Tc   1024
#define Nc   (Bc * Tc)        // 4096 tokens
#define Ec   768
#define FFc  3072
#define Vc   32000
#define Hc   6
#define HDc  128
#define Lc   6
#define NVc  ((size_t)Nc * Vc)

// ----------------------------------------------------------------------------
// Scratch (device globals; no allocation allowed)
// ----------------------------------------------------------------------------
__device__ float g_x [Nc * Ec];
__device__ float g_q [Nc * Ec];
__device__ float g_k [Nc * Ec];
__device__ float g_v [Nc * Ec];
__device__ float g_logits_fallback[Nc * (size_t)Vc];
__device__ int   g_idx[Nc];
__device__ int   g_tgt[Nc];
__device__ float g_rowloss[Nc];
__device__ int   g_is64;

__device__ __nv_bfloat16 g_h_hi [Nc * Ec],  g_h_lo [Nc * Ec];
__device__ __nv_bfloat16 g_o_hi [Nc * Ec],  g_o_lo [Nc * Ec];
__device__ __nv_bfloat16 g_ff_hi[Nc * FFc], g_ff_lo[Nc * FFc];

// transposed split weights: [N,K] bf16
__device__ __nv_bfloat16 g_WqT_hi[Lc * Ec * Ec],  g_WqT_lo[Lc * Ec * Ec];
__device__ __nv_bfloat16 g_WkT_hi[Lc * Ec * Ec],  g_WkT_lo[Lc * Ec * Ec];
__device__ __nv_bfloat16 g_WvT_hi[Lc * Ec * Ec],  g_WvT_lo[Lc * Ec * Ec];
__device__ __nv_bfloat16 g_WoT_hi[Lc * Ec * Ec],  g_WoT_lo[Lc * Ec * Ec];
__device__ __nv_bfloat16 g_w1T_hi[Lc * Ec * FFc], g_w1T_lo[Lc * Ec * FFc];
__device__ __nv_bfloat16 g_w2T_hi[Lc * Ec * FFc], g_w2T_lo[Lc * Ec * FFc];
__device__ __nv_bfloat16 g_WlmT_hi[(size_t)Vc * Ec], g_WlmT_lo[(size_t)Vc * Ec];

// ----------------------------------------------------------------------------
// PTX helpers (baseline ISA only: mma.sync / ldmatrix / cp.async)
// ----------------------------------------------------------------------------
__device__ __forceinline__ uint32_t smem_u32(const void* p) {
    uint32_t a;
    asm("{ .reg .u64 t; cvta.to.shared.u64 t, %1; cvt.u32.u64 %0, t; }"
        : "=r"(a) : "l"(p));
    return a;
}
__device__ __forceinline__ void cpa16(uint32_t dst, const void* src) {
    asm volatile("cp.async.cg.shared.global [%0], [%1], 16;\n"
                 :: "r"(dst), "l"(src) : "memory");
}
#define CP_COMMIT() asm volatile("cp.async.commit_group;\n" ::: "memory")
#define CP_WAIT(n)  asm volatile("cp.async.wait_group %0;\n" :: "n"(n) : "memory")

__device__ __forceinline__ void ldsm4(uint32_t* r, uint32_t addr) {
    asm volatile("ldmatrix.sync.aligned.m8n8.x4.shared.b16 {%0,%1,%2,%3}, [%4];"
        : "=r"(r[0]), "=r"(r[1]), "=r"(r[2]), "=r"(r[3]) : "r"(addr));
}
__device__ __forceinline__ void mma16816(float* d, const uint32_t* a, const uint32_t* b) {
    asm volatile("mma.sync.aligned.m16n8k16.row.col.f32.bf16.bf16.f32 "
        "{%0,%1,%2,%3}, {%4,%5,%6,%7}, {%8,%9}, {%0,%1,%2,%3};"
        : "+f"(d[0]), "+f"(d[1]), "+f"(d[2]), "+f"(d[3])
        : "r"(a[0]), "r"(a[1]), "r"(a[2]), "r"(a[3]), "r"(b[0]), "r"(b[1]));
}

// ----------------------------------------------------------------------------
// idx dtype detection + conversion
// ----------------------------------------------------------------------------
__global__ void detect_idx_kernel(const void* idx_raw) {
    const long long* p = (const long long*)idx_raw;
    int t = threadIdx.x;
    bool ok = true;
    for (int i = t; i < 64; i += 32) {
        long long v = p[i];
        if (v < 0 || v >= Vc) ok = false;
    }
    unsigned m = __ballot_sync(0xffffffffu, ok);
    if (t == 0) g_is64 = (m == 0xffffffffu) ? 1 : 0;
}

__global__ void convert_idx_kernel(const void* idxp, const void* tgtp) {
    int i = blockIdx.x * blockDim.x + threadIdx.x;
    if (i >= Nc) return;
    if (g_is64) {
        g_idx[i] = (int)((const long long*)idxp)[i];
        g_tgt[i] = (int)((const long long*)tgtp)[i];
    } else {
        g_idx[i] = ((const int*)idxp)[i];
        g_tgt[i] = ((const int*)tgtp)[i];
    }
}

// ----------------------------------------------------------------------------
// Embedding
// ----------------------------------------------------------------------------
__global__ void embed_kernel(const float* __restrict__ tok,
                             const float* __restrict__ pos,
                             float* __restrict__ x) {
    int gid = blockIdx.x * blockDim.x + threadIdx.x;
    if (gid >= Nc * Ec) return;
    int row = gid / Ec;
    int e   = gid - row * Ec;
    int t   = row & (Tc - 1);
    x[gid] = tok[(size_t)g_idx[row] * Ec + e] + pos[(size_t)t * Ec + e];
}

// ----------------------------------------------------------------------------
// Weight transpose + bf16 split: W[K,N] -> T_hi/T_lo[N,K]
// ----------------------------------------------------------------------------
__global__ __launch_bounds__(256) void wtr_kernel(const float* __restrict__ W,
                                                  __nv_bfloat16* __restrict__ Th,
                                                  __nv_bfloat16* __restrict__ Tl,
                                                  int K, int N) {
    __shared__ float tile[32][33];
    int n0 = blockIdx.x * 32, k0 = blockIdx.y * 32;
    int tx = threadIdx.x & 31, ty = threadIdx.x >> 5; // 32x8
    #pragma unroll
    for (int i = ty; i < 32; i += 8)
        tile[i][tx] = W[(size_t)(k0 + i) * N + n0 + tx];
    __syncthreads();
    #pragma unroll
    for (int i = ty; i < 32; i += 8) {
        float v = tile[tx][i];                    // W[k0+tx][n0+i]
        __nv_bfloat16 h = __float2bfloat16(v);
        size_t o = (size_t)(n0 + i) * K + k0 + tx;
        Th[o] = h;
        Tl[o] = __float2bfloat16(v - __bfloat162float(h));
    }
}

// ----------------------------------------------------------------------------
// LayerNorm -> split bf16 output
// ----------------------------------------------------------------------------
__global__ __launch_bounds__(256) void ln_split_kernel(const float* __restrict__ x,
                                                       const float* __restrict__ gw,
                                                       const float* __restrict__ gb,
                                                       __nv_bfloat16* __restrict__ ohi,
                                                       __nv_bfloat16* __restrict__ olo) {
    int row = blockIdx.x, t = threadIdx.x;
    const float* xr = x + (size_t)row * Ec;
    float v0 = xr[t], v1 = xr[t + 256], v2 = xr[t + 512];
    float s  = v0 + v1 + v2;
    float sq = fmaf(v0, v0, fmaf(v1, v1, v2 * v2));

    int lane = t & 31, wp = t >> 5;
    #pragma unroll
    for (int o = 16; o; o >>= 1) {
        s  += __shfl_xor_sync(0xffffffffu, s, o);
        sq += __shfl_xor_sync(0xffffffffu, sq, o);
    }
    __shared__ float shs[8], shq[8];
    if (lane == 0) { shs[wp] = s; shq[wp] = sq; }
    __syncthreads();
    s = 0.f; sq = 0.f;
    #pragma unroll
    for (int i = 0; i < 8; ++i) { s += shs[i]; sq += shq[i]; }

    const float invE = 1.0f / Ec;
    float mu   = s * invE;
    float var  = sq * invE - mu * mu;
    float rstd = rsqrtf(var + 1e-5f);

    size_t rb = (size_t)row * Ec;
    #pragma unroll
    for (int j = 0; j < 3; ++j) {
        int e = t + j * 256;
        float v = (j == 0 ? v0 : (j == 1 ? v1 : v2));
        float y = (v - mu) * rstd * gw[e] + gb[e];
        __nv_bfloat16 h = __float2bfloat16(y);
        ohi[rb + e] = h;
        olo[rb + e] = __float2bfloat16(y - __bfloat162float(h));
    }
}

// ----------------------------------------------------------------------------
// Tensor-core split-bf16 GEMM (mma.sync):
//   C[M,N] = (Ah+Al)[M,K] @ (Bh+Bl)^T,  B stored [N,K]
// CTA: 128x128 tile, BK=32, 256 threads = 8 warps (4m x 2n), warp: 32x64.
// smem rows padded to 80B for conflict-free ldmatrix.
// ----------------------------------------------------------------------------
#define TCG_F32       0   // Cf = acc + bias
#define TCG_RES       1   // Cf += acc + bias
#define TCG_RELUSPLIT 2   // t = relu(acc+bias); Chi/Clo = split(t)

#define TILE_B   10240           // 128 rows * 80B
#define STAGE_B  (4 * TILE_B)    // Ah, Al, Bh, Bl
#define GEMM_SMEM (2 * STAGE_B)  // 81920

template <int MODE>
__global__ __launch_bounds__(256) void tc_gemm(
    const __nv_bfloat16* __restrict__ Ah, const __nv_bfloat16* __restrict__ Al,
    const __nv_bfloat16* __restrict__ Bh, const __nv_bfloat16* __restrict__ Bl,
    const float* __restrict__ bias,
    float* __restrict__ Cf,
    __nv_bfloat16* __restrict__ Chi, __nv_bfloat16* __restrict__ Clo,
    int N, int K)
{
    extern __shared__ __align__(16) char sm[];
    uint32_t sb = smem_u32(sm);

    const int tid  = threadIdx.x;
    const int lane = tid & 31, wid = tid >> 5;
    const int row0 = blockIdx.y * 128, col0 = blockIdx.x * 128;
    const int m0w  = (wid & 3) * 32;         // warp row offset
    const int n0w  = (wid >> 2) * 64;        // warp col offset

    // global srcs for the cp.async loader: this thread's row & 32B chunk
    const int lrow  = tid >> 1;              // 0..127
    const int lby   = (tid & 1) * 32;        // byte offset in 64B row chunk
    const __nv_bfloat16* gA[4] = {
        Ah + (size_t)(row0 + lrow) * K,
        Al + (size_t)(row0 + lrow) * K,
        Bh + (size_t)(col0 + lrow) * K,
        Bl + (size_t)(col0 + lrow) * K };

    float acc[2][8][4];
    #pragma unroll
    for (int i = 0; i < 2; ++i)
        #pragma unroll
        for (int j = 0; j < 8; ++j)
            #pragma unroll
            for (int q = 0; q < 4; ++q) acc[i][j][q] = 0.f;

    const int NCk = K >> 5;   // K/32

    // ---- loader: one BK=32 chunk into stage s ----
    auto load_stage = [&](int c, int s) {
        uint32_t base = sb + s * STAGE_B;
        const char* off = (const char*)0 + (size_t)c * 64 + lby; // c*32 bf16
        #pragma unroll
        for (int tI = 0; tI < 4; ++tI) {
            uint32_t d = base + tI * TILE_B + lrow * 80 + lby;
            const char* g = (const char*)gA[tI] + (size_t)c * 64 + lby;
            cpa16(d, g);
            cpa16(d + 16, g + 16);
        }
        (void)off;
        CP_COMMIT();
    };

    load_stage(0, 0);

    // ldmatrix lane addressing (within a tile):
    //  A frag (m16k16): addr = row(m0+lane%16)*80 + (ks + (lane>>4)*8)*2
    //  B frag (n16k16): addr = row(n0+((lane>>4)<<3)+(lane&7))*80 + (ks+((lane>>3)&1)*8)*2
    const uint32_t aRowOff = (uint32_t)(lane & 15) * 80 + (uint32_t)(lane >> 4) * 16;
    const uint32_t bRowOff = (uint32_t)(((lane >> 4) << 3) + (lane & 7)) * 80
                           + (uint32_t)((lane >> 3) & 1) * 16;

    for (int c = 0; c < NCk; ++c) {
        int s = c & 1;
        if (c + 1 < NCk) load_stage(c + 1, s ^ 1);
        if (c + 1 < NCk) { CP_WAIT(1); } else { CP_WAIT(0); }
        __syncthreads();

        uint32_t base = sb + s * STAGE_B;
        uint32_t baseAh = base;
        uint32_t baseAl = base + TILE_B;
        uint32_t baseBh = base + 2 * TILE_B;
        uint32_t baseBl = base + 3 * TILE_B;

        #pragma unroll
        for (int ks = 0; ks < 2; ++ks) {
            uint32_t kOff = ks * 32;  // 16 bf16 = 32 bytes

            uint32_t ah[2][4], al[2][4];
            #pragma unroll
            for (int i = 0; i < 2; ++i) {
                uint32_t ro = (uint32_t)(m0w + i * 16) * 80 + kOff + aRowOff;
                ldsm4(ah[i], baseAh + ro);
                ldsm4(al[i], baseAl + ro);
            }
            uint32_t bh[8][2], bl[8][2];
            #pragma unroll
            for (int j = 0; j < 4; ++j) {
                uint32_t ro = (uint32_t)(n0w + j * 16) * 80 + kOff + bRowOff;
                uint32_t t4[4];
                ldsm4(t4, baseBh + ro);
                bh[2*j][0] = t4[0]; bh[2*j][1] = t4[1];
                bh[2*j+1][0] = t4[2]; bh[2*j+1][1] = t4[3];
                ldsm4(t4, baseBl + ro);
                bl[2*j][0] = t4[0]; bl[2*j][1] = t4[1];
                bl[2*j+1][0] = t4[2]; bl[2*j+1][1] = t4[3];
            }
            #pragma unroll
            for (int i = 0; i < 2; ++i)
                #pragma unroll
                for (int j = 0; j < 8; ++j) {
                    mma16816(acc[i][j], ah[i], bh[j]);
                    mma16816(acc[i][j], ah[i], bl[j]);
                    mma16816(acc[i][j], al[i], bh[j]);
                }
        }
        __syncthreads();
    }

    // ---- epilogue: direct global stores ----
    #pragma unroll
    for (int i = 0; i < 2; ++i) {
        #pragma unroll
        for (int j = 0; j < 8; ++j) {
            int cc = col0 + n0w + j * 8 + (lane & 3) * 2;
            float b0 = bias[cc], b1 = bias[cc + 1];
            #pragma unroll
            for (int half = 0; half < 2; ++half) {
                int rr = row0 + m0w + i * 16 + (lane >> 2) + half * 8;
                float v0 = acc[i][j][half * 2 + 0] + b0;
                float v1 = acc[i][j][half * 2 + 1] + b1;
                size_t gi = (size_t)rr * N + cc;
                if (MODE == TCG_F32) {
                    Cf[gi] = v0; Cf[gi + 1] = v1;
                } else if (MODE == TCG_RES) {
                    Cf[gi] += v0; Cf[gi + 1] += v1;
                } else {
                    v0 = fmaxf(v0, 0.f); v1 = fmaxf(v1, 0.f);
                    __nv_bfloat16 h0 = __float2bfloat16(v0);
                    __nv_bfloat16 h1 = __float2bfloat16(v1);
                    __nv_bfloat162 hp; hp.x = h0; hp.y = h1;
                    *(__nv_bfloat162*)(Chi + gi) = hp;
                    __nv_bfloat162 lp;
                    lp.x = __float2bfloat16(v0 - __bfloat162float(h0));
                    lp.y = __float2bfloat16(v1 - __bfloat162float(h1));
                    *(__nv_bfloat162*)(Clo + gi) = lp;
                }
            }
        }
    }
}

// ----------------------------------------------------------------------------
// Causal attention (fp32), epilogue writes split-bf16 o
// ----------------------------------------------------------------------------
__global__ __launch_bounds__(128) void attn_kernel(const float* __restrict__ Q,
                                                   const float* __restrict__ K,
                                                   const float* __restrict__ V,
                                                   __nv_bfloat16* __restrict__ Ohi,
                                                   __nv_bfloat16* __restrict__ Olo) {
    int qpos = blockIdx.x, h = blockIdx.y, b = blockIdx.z;
    int t = threadIdx.x, lane = t & 31, wp = t >> 5;

    __shared__ float sQ[128];
    __shared__ float sS[Tc];
    __shared__ float sT[32][129];
    __shared__ float sPart[32][4];
    __shared__ float sW[4];

    const size_t base = (size_t)b * Tc * Ec + (size_t)h * HDc;
    sQ[t] = Q[base + (size_t)qpos * Ec + t];
    __syncthreads();

    int nk = qpos + 1;
    const float scale = 0.08838834764831845f;

    for (int c0 = 0; c0 < nk; c0 += 32) {
        int rows = min(32, nk - c0);
        for (int r = wp; r < rows; r += 4) {
            const float* kr = K + base + (size_t)(c0 + r) * Ec;
            #pragma unroll
            for (int j = 0; j < 4; ++j) sT[r][lane + 32 * j] = kr[lane + 32 * j];
        }
        __syncthreads();
        if (lane < rows) {
            float sum = 0.f;
            #pragma unroll
            for (int dd = 0; dd < 32; ++dd)
                sum = fmaf(sQ[wp * 32 + dd], sT[lane][wp * 32 + dd], sum);
            sPart[lane][wp] = sum;
        }
        __syncthreads();
        if (t < rows)
            sS[c0 + t] = (sPart[t][0] + sPart[t][1] + sPart[t][2] + sPart[t][3]) * scale;
        __syncthreads();
    }

    float m = -1e30f;
    for (int i = t; i < nk; i += 128) m = fmaxf(m, sS[i]);
    #pragma unroll
    for (int o = 16; o; o >>= 1) m = fmaxf(m, __shfl_xor_sync(0xffffffffu, m, o));
    if (lane == 0) sW[wp] = m;
    __syncthreads();
    m = fmaxf(fmaxf(sW[0], sW[1]), fmaxf(sW[2], sW[3]));
    __syncthreads();

    float sum = 0.f;
    for (int i = t; i < nk; i += 128) {
        float p = expf(sS[i] - m);
        sS[i] = p;
        sum += p;
    }
    #pragma unroll
    for (int o = 16; o; o >>= 1) sum += __shfl_xor_sync(0xffffffffu, sum, o);
    if (lane == 0) sW[wp] = sum;
    __syncthreads();
    sum = sW[0] + sW[1] + sW[2] + sW[3];
    float inv = 1.0f / sum;

    float acc = 0.f;
    for (int c0 = 0; c0 < nk; c0 += 32) {
        int rows = min(32, nk - c0);
        __syncthreads();
        for (int r = wp; r < rows; r += 4) {
            const float* vr = V + base + (size_t)(c0 + r) * Ec;
            #pragma unroll
            for (int j = 0; j < 4; ++j) sT[r][lane + 32 * j] = vr[lane + 32 * j];
        }
        __syncthreads();
        for (int r = 0; r < rows; ++r)
            acc = fmaf(sS[c0 + r], sT[r][t], acc);
    }
    float ov = acc * inv;
    __nv_bfloat16 hv = __float2bfloat16(ov);
    size_t oi = base + (size_t)qpos * Ec + t;
    Ohi[oi] = hv;
    Olo[oi] = __float2bfloat16(ov - __bfloat162float(hv));
}

// ----------------------------------------------------------------------------
// Loss
// ----------------------------------------------------------------------------
__global__ __launch_bounds__(256) void loss_rows_kernel(const float* __restrict__ logits,
                                                        float* __restrict__ rowloss) {
    int row = blockIdx.x, t = threadIdx.x;
    int lane = t & 31, wp = t >> 5;
    const float* lr = logits + (size_t)row * Vc;
    __shared__ float sh[8];

    float m = -1e30f;
    for (int i = t; i < Vc; i += 256) m = fmaxf(m, lr[i]);
    #pragma unroll
    for (int o = 16; o; o >>= 1) m = fmaxf(m, __shfl_xor_sync(0xffffffffu, m, o));
    if (lane == 0) sh[wp] = m;
    __syncthreads();
    m = sh[0];
    #pragma unroll
    for (int i = 1; i < 8; ++i) m = fmaxf(m, sh[i]);
    __syncthreads();

    float s = 0.f;
    for (int i = t; i < Vc; i += 256) s += expf(lr[i] - m);
    #pragma unroll
    for (int o = 16; o; o >>= 1) s += __shfl_xor_sync(0xffffffffu, s, o);
    if (lane == 0) sh[wp] = s;
    __syncthreads();
    if (t == 0) {
        s = 0.f;
        #pragma unroll
        for (int i = 0; i < 8; ++i) s += sh[i];
        int tg = g_tgt[row];
        rowloss[row] = -(lr[tg] - m - logf(s));
    }
}

__global__ __launch_bounds__(256) void loss_final_kernel(const float* __restrict__ rowloss,
                                                         float* __restrict__ out) {
    int t = threadIdx.x, lane = t & 31, wp = t >> 5;
    float s = 0.f;
    for (int i = t; i < Nc; i += 256) s += rowloss[i];
    #pragma unroll
    for (int o = 16; o; o >>= 1) s += __shfl_xor_sync(0xffffffffu, s, o);
    __shared__ float sh[8];
    if (lane == 0) sh[wp] = s;
    __syncthreads();
    if (t == 0) {
        s = 0.f;
        #pragma unroll
        for (int i = 0; i < 8; ++i) s += sh[i];
        out[0] = s * (1.0f / Nc);
    }
}

// ----------------------------------------------------------------------------
// Host launch
// ----------------------------------------------------------------------------
static void* sym_addr(const void* s) {
    void* p = nullptr;
    cudaGetSymbolAddress(&p, s);
    return p;
}

extern "C" void kernel_launch(void* const* d_in, const int* in_sizes, int n_in,
                              void* d_out, int out_size) {
    const void*  idxp = d_in[0];
    const void*  tgtp = d_in[1];
    const float* tok  = (const float*)d_in[2];
    const float* pos  = (const float*)d_in[3];
    const float* Wq   = (const float*)d_in[4];
    const float* bq   = (const float*)d_in[5];
    const float* Wk   = (const float*)d_in[6];
    const float* bk   = (const float*)d_in[7];
    const float* Wv   = (const float*)d_in[8];
    const float* bv   = (const float*)d_in[9];
    const float* Wo   = (const float*)d_in[10];
    const float* bo   = (const float*)d_in[11];
    const float* w1   = (const float*)d_in[12];
    const float* b1   = (const float*)d_in[13];
    const float* w2   = (const float*)d_in[14];
    const float* b2   = (const float*)d_in[15];
    const float* ln1s = (const float*)d_in[16];
    const float* ln1b = (const float*)d_in[17];
    const float* ln2s = (const float*)d_in[18];
    const float* ln2b = (const float*)d_in[19];
    const float* lnfs = (const float*)d_in[20];
    const float* lnfb = (const float*)d_in[21];
    const float* Wlm  = (const float*)d_in[22];
    const float* blm  = (const float*)d_in[23];

    static int smem_set = 0;
    if (!smem_set) {
        cudaFuncSetAttribute(tc_gemm<TCG_F32>,       cudaFuncAttributeMaxDynamicSharedMemorySize, GEMM_SMEM);
        cudaFuncSetAttribute(tc_gemm<TCG_RES>,       cudaFuncAttributeMaxDynamicSharedMemorySize, GEMM_SMEM);
        cudaFuncSetAttribute(tc_gemm<TCG_RELUSPLIT>, cudaFuncAttributeMaxDynamicSharedMemorySize, GEMM_SMEM);
        smem_set = 1;
    }

    float* x  = (float*)sym_addr(g_x);
    float* q  = (float*)sym_addr(g_q);
    float* k  = (float*)sym_addr(g_k);
    float* v  = (float*)sym_addr(g_v);
    float* rowloss = (float*)sym_addr(g_rowloss);
    __nv_bfloat16* h_hi  = (__nv_bfloat16*)sym_addr(g_h_hi);
    __nv_bfloat16* h_lo  = (__nv_bfloat16*)sym_addr(g_h_lo);
    __nv_bfloat16* o_hi  = (__nv_bfloat16*)sym_addr(g_o_hi);
    __nv_bfloat16* o_lo  = (__nv_bfloat16*)sym_addr(g_o_lo);
    __nv_bfloat16* ff_hi = (__nv_bfloat16*)sym_addr(g_ff_hi);
    __nv_bfloat16* ff_lo = (__nv_bfloat16*)sym_addr(g_ff_lo);

    __nv_bfloat16* WqTh = (__nv_bfloat16*)sym_addr(g_WqT_hi), *WqTl = (__nv_bfloat16*)sym_addr(g_WqT_lo);
    __nv_bfloat16* WkTh = (__nv_bfloat16*)sym_addr(g_WkT_hi), *WkTl = (__nv_bfloat16*)sym_addr(g_WkT_lo);
    __nv_bfloat16* WvTh = (__nv_bfloat16*)sym_addr(g_WvT_hi), *WvTl = (__nv_bfloat16*)sym_addr(g_WvT_lo);
    __nv_bfloat16* WoTh = (__nv_bfloat16*)sym_addr(g_WoT_hi), *WoTl = (__nv_bfloat16*)sym_addr(g_WoT_lo);
    __nv_bfloat16* w1Th = (__nv_bfloat16*)sym_addr(g_w1T_hi), *w1Tl = (__nv_bfloat16*)sym_addr(g_w1T_lo);
    __nv_bfloat16* w2Th = (__nv_bfloat16*)sym_addr(g_w2T_hi), *w2Tl = (__nv_bfloat16*)sym_addr(g_w2T_lo);
    __nv_bfloat16* WlmTh = (__nv_bfloat16*)sym_addr(g_WlmT_hi), *WlmTl = (__nv_bfloat16*)sym_addr(g_WlmT_lo);

    float* logits = ((size_t)out_size >= NVc) ? (float*)d_out
                                              : (float*)sym_addr(g_logits_fallback);

    // weight transpose + split
    {
        dim3 bEE(Ec / 32, Ec / 32);
        dim3 b1g(FFc / 32, Ec / 32);
        dim3 b2g(Ec / 32, FFc / 32);
        dim3 bLM(Vc / 32, Ec / 32);
        for (int l = 0; l < Lc; ++l) {
            size_t oEE = (size_t)l * Ec * Ec;
            size_t oFF = (size_t)l * Ec * FFc;
            wtr_kernel<<<bEE, 256>>>(Wq + oEE, WqTh + oEE, WqTl + oEE, Ec, Ec);
            wtr_kernel<<<bEE, 256>>>(Wk + oEE, WkTh + oEE, WkTl + oEE, Ec, Ec);
            wtr_kernel<<<bEE, 256>>>(Wv + oEE, WvTh + oEE, WvTl + oEE, Ec, Ec);
            wtr_kernel<<<bEE, 256>>>(Wo + oEE, WoTh + oEE, WoTl + oEE, Ec, Ec);
            wtr_kernel<<<b1g, 256>>>(w1 + oFF, w1Th + oFF, w1Tl + oFF, Ec, FFc);
            wtr_kernel<<<b2g, 256>>>(w2 + oFF, w2Th + oFF, w2Tl + oFF, FFc, Ec);
        }
        wtr_kernel<<<bLM, 256>>>(Wlm, WlmTh, WlmTl, Ec, Vc);
    }

    detect_idx_kernel<<<1, 32>>>(idxp);
    convert_idx_kernel<<<(Nc + 255) / 256, 256>>>(idxp, tgtp);
    embed_kernel<<<(Nc * Ec + 255) / 256, 256>>>(tok, pos, x);

    dim3 gE(Ec / 128, Nc / 128);    // 6 x 32
    dim3 gF(FFc / 128, Nc / 128);   // 24 x 32
    dim3 gV(Vc / 128, Nc / 128);    // 250 x 32
    dim3 gAttn(Tc, Hc, Bc);

    for (int l = 0; l < Lc; ++l) {
        size_t oEE = (size_t)l * Ec * Ec;
        size_t oFF = (size_t)l * Ec * FFc;

        ln_split_kernel<<<Nc, 256>>>(x, ln1s + l * Ec, ln1b + l * Ec, h_hi, h_lo);
        tc_gemm<TCG_F32><<<gE, 256, GEMM_SMEM>>>(h_hi, h_lo, WqTh + oEE, WqTl + oEE,
                                                 bq + l * Ec, q, nullptr, nullptr, Ec, Ec);
        tc_gemm<TCG_F32><<<gE, 256, GEMM_SMEM>>>(h_hi, h_lo, WkTh + oEE, WkTl + oEE,
                                                 bk + l * Ec, k, nullptr, nullptr, Ec, Ec);
        tc_gemm<TCG_F32><<<gE, 256, GEMM_SMEM>>>(h_hi, h_lo, WvTh + oEE, WvTl + oEE,
                                                 bv + l * Ec, v, nullptr, nullptr, Ec, Ec);
        attn_kernel<<<gAttn, 128>>>(q, k, v, o_hi, o_lo);
        tc_gemm<TCG_RES><<<gE, 256, GEMM_SMEM>>>(o_hi, o_lo, WoTh + oEE, WoTl + oEE,
                                                 bo + l * Ec, x, nullptr, nullptr, Ec, Ec);
        ln_split_kernel<<<Nc, 256>>>(x, ln2s + l * Ec, ln2b + l * Ec, h_hi, h_lo);
        tc_gemm<TCG_RELUSPLIT><<<gF, 256, GEMM_SMEM>>>(h_hi, h_lo, w1Th + oFF, w1Tl + oFF,
                                                       b1 + l * FFc, nullptr, ff_hi, ff_lo, FFc, Ec);
        tc_gemm<TCG_RES><<<gE, 256, GEMM_SMEM>>>(ff_hi, ff_lo, w2Th + oFF, w2Tl + oFF,
                                                 b2 + l * Ec, x, nullptr, nullptr, Ec, FFc);
    }

    ln_split_kernel<<<Nc, 256>>>(x, lnfs, lnfb, h_hi, h_lo);
    tc_gemm<TCG_F32><<<gV, 256, GEMM_SMEM>>>(h_hi, h_lo, WlmTh, WlmTl,
                                             blm, logits, nullptr, nullptr, Vc, Ec);

    loss_rows_kernel<<<Nc, 256>>>(logits, rowloss);
    if ((size_t)out_size >= NVc + 1) {
        loss_final_kernel<<<1, 256>>>(rowloss, (float*)d_out + NVc);
    } else if ((size_t)out_size < NVc) {
        loss_final_kernel<<<1, 256>>>(rowloss, (float*)d_out);
    }
}